// round 1
// baseline (speedup 1.0000x reference)
#include <cuda_runtime.h>
#include <math.h>

#define Bz   2048
#define Tz   64
#define HZ   128   // HID
#define FZ   128   // FEAT
#define BB   16    // batch rows per k_cell CTA

// Scratch (static device globals — no allocation in kernel_launch)
__device__ float g_sP[(size_t)Bz * Tz * FZ];   // H @ W1_h + b1   (64 MB)
__device__ float g_d[Bz * HZ];
__device__ float g_c[Bz * HZ];
__device__ float g_ctx[Bz * HZ];
__device__ float g_a[Bz * FZ];                 // dc @ W1_dc (per step)

__device__ __forceinline__ float wred(float v) {
#pragma unroll
    for (int o = 16; o > 0; o >>= 1) v += __shfl_xor_sync(0xffffffffu, v, o);
    return v;
}

// tanh(x) = 1 - 2/(exp(2x)+1); saturates correctly at +-inf, ~1e-7 rel err.
__device__ __forceinline__ float fast_tanh(float x) {
    float e = __expf(2.0f * x);
    return 1.0f - __fdividef(2.0f, e + 1.0f);
}
__device__ __forceinline__ float sigm(float x) {
    return __fdividef(1.0f, 1.0f + __expf(-x));
}

// ---------------------------------------------------------------------------
// k_init: g_sP[b,t,f] = sum_h H[b,t,h] * W1[256+h, f] + b1[f];  zero d,c,a.
// Grid: Bz blocks x 256 threads.
// ---------------------------------------------------------------------------
__global__ void k_init(const float* __restrict__ H,
                       const float* __restrict__ W1,
                       const float* __restrict__ b1) {
    __shared__ float sH[Tz * HZ];  // 32 KB
    int b = blockIdx.x, tid = threadIdx.x;
    const float* Hb = H + (size_t)b * Tz * HZ;
    for (int i = tid; i < Tz * HZ; i += 256) sH[i] = Hb[i];
    if (tid < HZ) {
        g_d[b * HZ + tid] = 0.0f;
        g_c[b * HZ + tid] = 0.0f;
        g_a[b * FZ + tid] = 0.0f;   // dc=0 -> a=0
    }
    __syncthreads();

    int f = tid & 127, th = tid >> 7;
    float bias = __ldg(&b1[f]);
    for (int t = th; t < Tz; t += 2) {
        float acc = bias;
        const float* hrow = &sH[t * HZ];
#pragma unroll 4
        for (int h = 0; h < HZ; ++h)
            acc += hrow[h] * __ldg(&W1[(256 + h) * FZ + f]);
        g_sP[((size_t)b * Tz + t) * FZ + f] = acc;
    }
}

// ---------------------------------------------------------------------------
// k_attn: per batch row b:
//   e[t]  = sum_f tanh(sP[b,t,f] + a[b,f]) * W2[f]      (b2 cancels in softmax)
//   beta  = softmax_t(e)
//   ctx[f]= sum_t beta[t] * H[b,t,f]
// Grid: Bz blocks x 128 threads.
// ---------------------------------------------------------------------------
__global__ void k_attn(const float* __restrict__ H,
                       const float* __restrict__ W2) {
    __shared__ float sa[FZ], sw2[FZ], se[Tz];
    int b = blockIdx.x, tid = threadIdx.x;
    sa[tid]  = g_a[b * FZ + tid];
    sw2[tid] = __ldg(&W2[tid]);
    __syncthreads();

    int w = tid >> 5, lane = tid & 31;
    const float* pb = &g_sP[(size_t)b * Tz * FZ];
#pragma unroll 4
    for (int tt = 0; tt < 16; ++tt) {
        int t = w * 16 + tt;
        const float* p = pb + t * FZ;
        float s = 0.0f;
#pragma unroll
        for (int k = 0; k < 4; ++k) {
            int f = lane + 32 * k;
            s += fast_tanh(p[f] + sa[f]) * sw2[f];
        }
        s = wred(s);
        if (lane == 0) se[t] = s;
    }
    __syncthreads();

    if (w == 0) {  // softmax over 64 by warp 0
        float a0 = se[lane], a1 = se[lane + 32];
        float m = fmaxf(a0, a1);
#pragma unroll
        for (int o = 16; o > 0; o >>= 1) m = fmaxf(m, __shfl_xor_sync(0xffffffffu, m, o));
        float e0 = __expf(a0 - m), e1 = __expf(a1 - m);
        float s = wred(e0 + e1);
        float inv = __fdividef(1.0f, s);
        se[lane]      = e0 * inv;
        se[lane + 32] = e1 * inv;
    }
    __syncthreads();

    float acc = 0.0f;
    const float* Hb = H + (size_t)b * Tz * HZ;
#pragma unroll 8
    for (int t = 0; t < Tz; ++t)
        acc += se[t] * Hb[t * HZ + tid];
    g_ctx[b * HZ + tid] = acc;
}

// ---------------------------------------------------------------------------
// k_cell: per batch tile of BB=16 rows:
//   y_tilde = ctx . fcW[0:128] + y_t * fcW[128] + fcb
//   gates   = y_tilde*W_ih + d @ W_hh^T + b_ih + b_hh   (512 outputs)
//   LSTM pointwise update of d,c; then a_next = [d,c] @ W1[:256]
// Grid: Bz/BB blocks x 256 threads.
// ---------------------------------------------------------------------------
__global__ void k_cell(const float* __restrict__ Y,
                       const float* __restrict__ W_ih,
                       const float* __restrict__ Whh,
                       const float* __restrict__ b_ih,
                       const float* __restrict__ b_hh,
                       const float* __restrict__ fcW,
                       const float* __restrict__ fcb,
                       const float* __restrict__ W1,
                       int step) {
    __shared__ float sd[BB * HZ];    // d_old
    __shared__ float sdn[BB * HZ];   // d_new
    __shared__ float scn[BB * HZ];   // c_new
    __shared__ float sy[BB];
    int tid = threadIdx.x;
    int b0 = blockIdx.x * BB;

    for (int i = tid; i < BB * HZ; i += 256) sd[i] = g_d[b0 * HZ + i];

    int w = tid >> 5, lane = tid & 31;
    // y_tilde: warp w handles local rows 2w, 2w+1
    for (int bl = 2 * w; bl < 2 * w + 2; ++bl) {
        int b = b0 + bl;
        const float* cx = &g_ctx[b * HZ];
        float s = 0.0f;
#pragma unroll
        for (int k = 0; k < 4; ++k) {
            int f = lane + 32 * k;
            s += cx[f] * __ldg(&fcW[f]);
        }
        s = wred(s);
        if (lane == 0)
            sy[bl] = s + __ldg(&Y[b * Tz + step]) * __ldg(&fcW[HZ]) + __ldg(&fcb[0]);
    }
    __syncthreads();

    int jj = tid & 127, bb2 = tid >> 7;  // gate h-index, batch split
    float wih0 = __ldg(&W_ih[jj]);
    float wih1 = __ldg(&W_ih[jj + 128]);
    float wih2 = __ldg(&W_ih[jj + 256]);
    float wih3 = __ldg(&W_ih[jj + 384]);
    float bia0 = __ldg(&b_ih[jj])       + __ldg(&b_hh[jj]);
    float bia1 = __ldg(&b_ih[jj + 128]) + __ldg(&b_hh[jj + 128]);
    float bia2 = __ldg(&b_ih[jj + 256]) + __ldg(&b_hh[jj + 256]);
    float bia3 = __ldg(&b_ih[jj + 384]) + __ldg(&b_hh[jj + 384]);

    const float* w0 = Whh + (size_t)jj * HZ;
    const float* w1 = Whh + (size_t)(jj + 128) * HZ;
    const float* w2 = Whh + (size_t)(jj + 256) * HZ;
    const float* w3 = Whh + (size_t)(jj + 384) * HZ;

    float acc[8][4];
#pragma unroll
    for (int r = 0; r < 8; ++r)
#pragma unroll
        for (int g = 0; g < 4; ++g) acc[r][g] = 0.0f;

#pragma unroll 2
    for (int h = 0; h < HZ; ++h) {
        float v0 = __ldg(&w0[h]);
        float v1 = __ldg(&w1[h]);
        float v2 = __ldg(&w2[h]);
        float v3 = __ldg(&w3[h]);
#pragma unroll
        for (int r = 0; r < 8; ++r) {
            float dv = sd[(bb2 + 2 * r) * HZ + h];
            acc[r][0] += dv * v0;
            acc[r][1] += dv * v1;
            acc[r][2] += dv * v2;
            acc[r][3] += dv * v3;
        }
    }

#pragma unroll
    for (int r = 0; r < 8; ++r) {
        int bl = bb2 + 2 * r;
        int b  = b0 + bl;
        float yt = sy[bl];
        float gi = acc[r][0] + yt * wih0 + bia0;
        float gf = acc[r][1] + yt * wih1 + bia1;
        float gg = acc[r][2] + yt * wih2 + bia2;
        float go = acc[r][3] + yt * wih3 + bia3;
        float cold = g_c[b * HZ + jj];
        float cn = sigm(gf) * cold + sigm(gi) * fast_tanh(gg);
        float dn = sigm(go) * fast_tanh(cn);
        g_c[b * HZ + jj] = cn;
        g_d[b * HZ + jj] = dn;
        sdn[bl * HZ + jj] = dn;
        scn[bl * HZ + jj] = cn;
    }
    __syncthreads();

    // a_next[b, jj] = sum_h dn[b,h]*W1[h,jj] + cn[b,h]*W1[128+h,jj]
    float aacc[8];
#pragma unroll
    for (int r = 0; r < 8; ++r) aacc[r] = 0.0f;
#pragma unroll 2
    for (int h = 0; h < HZ; ++h) {
        float wd = __ldg(&W1[h * FZ + jj]);
        float wc = __ldg(&W1[(128 + h) * FZ + jj]);
#pragma unroll
        for (int r = 0; r < 8; ++r) {
            int bl = bb2 + 2 * r;
            aacc[r] += sdn[bl * HZ + h] * wd + scn[bl * HZ + h] * wc;
        }
    }
#pragma unroll
    for (int r = 0; r < 8; ++r)
        g_a[(b0 + bb2 + 2 * r) * FZ + jj] = aacc[r];
}

// ---------------------------------------------------------------------------
// k_final: out[b] = d[b,:].fcfW[0:128] + ctx[b,:].fcfW[128:256] + fcfb
// Grid: Bz/8 blocks x 256 threads (1 warp per batch row).
// ---------------------------------------------------------------------------
__global__ void k_final(const float* __restrict__ fcfW,
                        const float* __restrict__ fcfb,
                        float* __restrict__ out) {
    int tid = threadIdx.x, w = tid >> 5, lane = tid & 31;
    int b = blockIdx.x * 8 + w;
    const float* db = &g_d[b * HZ];
    const float* cb = &g_ctx[b * HZ];
    float s = 0.0f;
#pragma unroll
    for (int k = 0; k < 4; ++k) {
        int f = lane + 32 * k;
        s += db[f] * __ldg(&fcfW[f]) + cb[f] * __ldg(&fcfW[128 + f]);
    }
    s = wred(s);
    if (lane == 0) out[b] = s + __ldg(&fcfb[0]);
}

extern "C" void kernel_launch(void* const* d_in, const int* in_sizes, int n_in,
                              void* d_out, int out_size) {
    (void)in_sizes; (void)n_in; (void)out_size;
    const float* H    = (const float*)d_in[0];
    const float* Y    = (const float*)d_in[1];
    const float* W1   = (const float*)d_in[2];
    const float* b1   = (const float*)d_in[3];
    const float* W2   = (const float*)d_in[4];
    // d_in[5] = attn_b2: constant shift, cancels in softmax.
    const float* W_ih = (const float*)d_in[6];
    const float* Whh  = (const float*)d_in[7];
    const float* b_ih = (const float*)d_in[8];
    const float* b_hh = (const float*)d_in[9];
    const float* fcW  = (const float*)d_in[10];
    const float* fcb  = (const float*)d_in[11];
    const float* fcfW = (const float*)d_in[12];
    const float* fcfb = (const float*)d_in[13];
    float* out = (float*)d_out;

    k_init<<<Bz, 256>>>(H, W1, b1);
    for (int t = 0; t < Tz; ++t) {
        k_attn<<<Bz, 128>>>(H, W2);
        k_cell<<<Bz / BB, 256>>>(Y, W_ih, Whh, b_ih, b_hh, fcW, fcb, W1, t);
    }
    k_final<<<Bz / 8, 256>>>(fcfW, fcfb, out);
}

// round 2
// speedup vs baseline: 2.3454x; 2.3454x over previous
#include <cuda_runtime.h>
#include <cuda_fp16.h>
#include <math.h>

#define Bz   2048
#define Tz   64
#define HZ   128   // HID
#define FZ   128   // FEAT
#define BB   16    // batch rows per k_cell CTA

typedef unsigned long long ull;

// ---------------- scratch (static device globals) ----------------
__device__ __half g_sPh[(size_t)Bz * Tz * FZ];   // fp16 H@W1_h + b1  (32 MB)
__device__ __half g_Hh [(size_t)Bz * Tz * HZ];   // fp16 copy of H    (32 MB)
__device__ float  g_d[Bz * HZ];
__device__ float  g_c[Bz * HZ];
__device__ float  g_ctx[Bz * HZ];
__device__ float  g_a[Bz * FZ];                  // dc @ W1_dc per step (fp32)
__device__ float  g_WhT[HZ * 4 * HZ];            // Whh transposed [128h][512j]
__device__ ull    g_WT2[HZ * 2 * FZ];            // [h][pair][jj] packed (gi,gf)/(gg,go) weights
__device__ ull    g_W12[HZ * FZ];                // [h][jj] packed (W1d, W1c)

// ---------------- helpers ----------------
__device__ __forceinline__ float wred(float v) {
#pragma unroll
    for (int o = 16; o > 0; o >>= 1) v += __shfl_xor_sync(0xffffffffu, v, o);
    return v;
}
__device__ __forceinline__ float fast_tanh(float x) {       // accurate (~1e-7)
    float e = __expf(2.0f * x);
    return 1.0f - __fdividef(2.0f, e + 1.0f);
}
__device__ __forceinline__ float tanh_approx(float x) {     // MUFU.TANH, ~2^-11
    float r; asm("tanh.approx.f32 %0, %1;" : "=f"(r) : "f"(x)); return r;
}
__device__ __forceinline__ float sigm(float x) {
    return __fdividef(1.0f, 1.0f + __expf(-x));
}
__device__ __forceinline__ ull pack2(float a, float b) {
    return (ull)__float_as_uint(a) | ((ull)__float_as_uint(b) << 32);
}
__device__ __forceinline__ float lo2(ull v) { return __uint_as_float((unsigned)v); }
__device__ __forceinline__ float hi2(ull v) { return __uint_as_float((unsigned)(v >> 32)); }
__device__ __forceinline__ void ffma2(ull &acc, ull a, ull b) {
    asm("fma.rn.f32x2 %0, %1, %2, %0;" : "+l"(acc) : "l"(a), "l"(b));
}

// ---------------------------------------------------------------------------
// k_tr: tiled transpose Whh [512,128] -> g_WhT [128,512]
// ---------------------------------------------------------------------------
__global__ void k_tr(const float* __restrict__ Whh) {
    __shared__ float tile[32][33];
    int tx = threadIdx.x, ty = threadIdx.y;
    int x = blockIdx.x * 32 + tx;            // h
    int y = blockIdx.y * 32 + ty;            // j
#pragma unroll
    for (int k = 0; k < 32; k += 8)
        tile[ty + k][tx] = Whh[(y + k) * HZ + x];
    __syncthreads();
    int x2 = blockIdx.y * 32 + tx;           // j
    int y2 = blockIdx.x * 32 + ty;           // h
#pragma unroll
    for (int k = 0; k < 32; k += 8)
        g_WhT[(y2 + k) * 512 + x2] = tile[tx][ty + k];
}

// ---------------------------------------------------------------------------
// k_pack: build packed weight tables (all coalesced)
// ---------------------------------------------------------------------------
__global__ void k_pack(const float* __restrict__ W1) {
    int idx = blockIdx.x * 256 + threadIdx.x;
    if (idx < HZ * 2 * FZ) {                  // 32768: WT2
        int jj = idx & 127, pair = (idx >> 7) & 1, h = idx >> 8;
        float v0 = g_WhT[h * 512 + pair * 256 + jj];
        float v1 = g_WhT[h * 512 + pair * 256 + 128 + jj];
        g_WT2[idx] = pack2(v0, v1);
    } else {                                  // 16384: W12
        int j = idx - HZ * 2 * FZ;
        int jj = j & 127, h = j >> 7;
        g_W12[j] = pack2(__ldg(&W1[h * FZ + jj]), __ldg(&W1[(128 + h) * FZ + jj]));
    }
}

// ---------------------------------------------------------------------------
// k_init: g_sPh[b,t,f] = fp16( sum_h H[b,t,h]*W1[256+h,f] + b1[f] )
//         g_Hh = fp16(H); zero d,c,a.    Grid Bz x 256.
// ---------------------------------------------------------------------------
__global__ void k_init(const float* __restrict__ H,
                       const float* __restrict__ W1,
                       const float* __restrict__ b1) {
    __shared__ float sHT[HZ * 66];           // [h][t] padded, 33 KB
    int b = blockIdx.x, tid = threadIdx.x;
    const float* Hb = H + (size_t)b * Tz * HZ;
    for (int i = tid; i < Tz * HZ; i += 256) {
        int t = i >> 7, h = i & 127;
        float v = Hb[i];
        sHT[h * 66 + t] = v;
        g_Hh[(size_t)b * Tz * HZ + i] = __float2half(v);
    }
    if (tid < HZ) {
        g_d[b * HZ + tid] = 0.0f;
        g_c[b * HZ + tid] = 0.0f;
        g_a[b * FZ + tid] = 0.0f;
    }
    __syncthreads();

    int f = tid & 127, half_id = tid >> 7;   // each thread: 16 t-pairs
    float bias = __ldg(&b1[f]);
    ull acc[16];
#pragma unroll
    for (int k = 0; k < 16; ++k) acc[k] = pack2(bias, bias);

#pragma unroll 2
    for (int h = 0; h < HZ; ++h) {
        float w = __ldg(&W1[(256 + h) * FZ + f]);
        ull ww = pack2(w, w);
        const ull* row = (const ull*)&sHT[h * 66];
#pragma unroll
        for (int k = 0; k < 16; ++k)
            ffma2(acc[k], row[half_id * 16 + k], ww);
    }
    __half* outb = g_sPh + (size_t)b * Tz * FZ;
#pragma unroll
    for (int k = 0; k < 16; ++k) {
        int t = (half_id * 16 + k) * 2;
        outb[t * FZ + f]       = __float2half(lo2(acc[k]));
        outb[(t + 1) * FZ + f] = __float2half(hi2(acc[k]));
    }
}

// ---------------------------------------------------------------------------
// k_attn: e[t] = sum_f tanh(sP+a)*W2; beta=softmax; ctx = sum_t beta*H
// Grid Bz x 128.
// ---------------------------------------------------------------------------
__global__ void k_attn(const float* __restrict__ W2) {
    __shared__ float sa[FZ], sw2[FZ], se[Tz];
    int b = blockIdx.x, tid = threadIdx.x;
    sa[tid]  = g_a[b * FZ + tid];
    sw2[tid] = __ldg(&W2[tid]);
    __syncthreads();

    int w = tid >> 5, lane = tid & 31;
    const __half2* pb = (const __half2*)(g_sPh + (size_t)b * Tz * FZ);
#pragma unroll 2
    for (int tt = 0; tt < 16; ++tt) {
        int t = w * 16 + tt;
        const __half2* p = pb + t * (FZ / 2);
        float s = 0.0f;
#pragma unroll
        for (int k = 0; k < 2; ++k) {
            int i = lane + 32 * k;
            float2 v = __half22float2(p[i]);
            int f = 2 * i;
            s += tanh_approx(v.x + sa[f])     * sw2[f];
            s += tanh_approx(v.y + sa[f + 1]) * sw2[f + 1];
        }
        s = wred(s);
        if (lane == 0) se[t] = s;
    }
    __syncthreads();

    if (w == 0) {
        float a0 = se[lane], a1 = se[lane + 32];
        float m = fmaxf(a0, a1);
#pragma unroll
        for (int o = 16; o > 0; o >>= 1) m = fmaxf(m, __shfl_xor_sync(0xffffffffu, m, o));
        float e0 = __expf(a0 - m), e1 = __expf(a1 - m);
        float s = wred(e0 + e1);
        float inv = __fdividef(1.0f, s);
        se[lane]      = e0 * inv;
        se[lane + 32] = e1 * inv;
    }
    __syncthreads();

    float acc = 0.0f;
    const __half* Hb = g_Hh + (size_t)b * Tz * HZ;
#pragma unroll 8
    for (int t = 0; t < Tz; ++t)
        acc += se[t] * __half2float(Hb[t * HZ + tid]);
    g_ctx[b * HZ + tid] = acc;
}

// ---------------------------------------------------------------------------
// k_cell: gates GEMV (coalesced, f32x2), LSTM pointwise, a_next GEMV.
// Grid Bz/BB x 256.
// ---------------------------------------------------------------------------
__global__ void k_cell(const float* __restrict__ Y,
                       const float* __restrict__ W_ih,
                       const float* __restrict__ b_ih,
                       const float* __restrict__ b_hh,
                       const float* __restrict__ fcW,
                       const float* __restrict__ fcb,
                       int step) {
    __shared__ ull   sdd[BB * HZ];    // (d,d) duplicated, 16 KB
    __shared__ ull   sdc[BB * HZ];    // (d_new, c_new), 16 KB
    __shared__ float sy[BB];
    int tid = threadIdx.x;
    int b0 = blockIdx.x * BB;

    for (int i = tid; i < BB * HZ; i += 256) {
        float v = g_d[b0 * HZ + i];
        sdd[i] = pack2(v, v);
    }

    int w = tid >> 5, lane = tid & 31;
    for (int bl = 2 * w; bl < 2 * w + 2; ++bl) {
        int b = b0 + bl;
        const float* cx = &g_ctx[b * HZ];
        float s = 0.0f;
#pragma unroll
        for (int k = 0; k < 4; ++k) {
            int f = lane + 32 * k;
            s += cx[f] * __ldg(&fcW[f]);
        }
        s = wred(s);
        if (lane == 0)
            sy[bl] = s + __ldg(&Y[b * Tz + step]) * __ldg(&fcW[HZ]) + __ldg(&fcb[0]);
    }
    __syncthreads();

    int jj = tid & 127, bb2 = tid >> 7;
    float wih0 = __ldg(&W_ih[jj]);
    float wih1 = __ldg(&W_ih[jj + 128]);
    float wih2 = __ldg(&W_ih[jj + 256]);
    float wih3 = __ldg(&W_ih[jj + 384]);
    float bia0 = __ldg(&b_ih[jj])       + __ldg(&b_hh[jj]);
    float bia1 = __ldg(&b_ih[jj + 128]) + __ldg(&b_hh[jj + 128]);
    float bia2 = __ldg(&b_ih[jj + 256]) + __ldg(&b_hh[jj + 256]);
    float bia3 = __ldg(&b_ih[jj + 384]) + __ldg(&b_hh[jj + 384]);

    ull acc[8][2];
#pragma unroll
    for (int r = 0; r < 8; ++r) { acc[r][0] = 0ull; acc[r][1] = 0ull; }

#pragma unroll 2
    for (int h = 0; h < HZ; ++h) {
        ull w01 = __ldg(&g_WT2[(h * 2 + 0) * 128 + jj]);   // (w_i, w_f) coalesced
        ull w23 = __ldg(&g_WT2[(h * 2 + 1) * 128 + jj]);   // (w_g, w_o)
#pragma unroll
        for (int r = 0; r < 8; ++r) {
            ull dv = sdd[(bb2 + 2 * r) * HZ + h];          // broadcast LDS.64
            ffma2(acc[r][0], dv, w01);
            ffma2(acc[r][1], dv, w23);
        }
    }

#pragma unroll
    for (int r = 0; r < 8; ++r) {
        int bl = bb2 + 2 * r;
        int b  = b0 + bl;
        float yt = sy[bl];
        float gi = lo2(acc[r][0]) + yt * wih0 + bia0;
        float gf = hi2(acc[r][0]) + yt * wih1 + bia1;
        float gg = lo2(acc[r][1]) + yt * wih2 + bia2;
        float go = hi2(acc[r][1]) + yt * wih3 + bia3;
        float cold = g_c[b * HZ + jj];
        float cn = sigm(gf) * cold + sigm(gi) * fast_tanh(gg);
        float dn = sigm(go) * fast_tanh(cn);
        g_c[b * HZ + jj] = cn;
        g_d[b * HZ + jj] = dn;
        sdc[bl * HZ + jj] = pack2(dn, cn);
    }
    __syncthreads();

    // a_next[b,jj] = sum_h dn*W1[h,jj] + cn*W1[128+h,jj]
    ull aa[8];
#pragma unroll
    for (int r = 0; r < 8; ++r) aa[r] = 0ull;
#pragma unroll 2
    for (int h = 0; h < HZ; ++h) {
        ull wv = __ldg(&g_W12[h * 128 + jj]);              // (W1d, W1c) coalesced
#pragma unroll
        for (int r = 0; r < 8; ++r) {
            ull dc = sdc[(bb2 + 2 * r) * HZ + h];          // broadcast
            ffma2(aa[r], dc, wv);
        }
    }
#pragma unroll
    for (int r = 0; r < 8; ++r)
        g_a[(b0 + bb2 + 2 * r) * FZ + jj] = lo2(aa[r]) + hi2(aa[r]);
}

// ---------------------------------------------------------------------------
// k_final: out[b] = d.fcfW[0:128] + ctx.fcfW[128:256] + fcfb
// ---------------------------------------------------------------------------
__global__ void k_final(const float* __restrict__ fcfW,
                        const float* __restrict__ fcfb,
                        float* __restrict__ out) {
    int tid = threadIdx.x, w = tid >> 5, lane = tid & 31;
    int b = blockIdx.x * 8 + w;
    const float* db = &g_d[b * HZ];
    const float* cb = &g_ctx[b * HZ];
    float s = 0.0f;
#pragma unroll
    for (int k = 0; k < 4; ++k) {
        int f = lane + 32 * k;
        s += db[f] * __ldg(&fcfW[f]) + cb[f] * __ldg(&fcfW[128 + f]);
    }
    s = wred(s);
    if (lane == 0) out[b] = s + __ldg(&fcfb[0]);
}

extern "C" void kernel_launch(void* const* d_in, const int* in_sizes, int n_in,
                              void* d_out, int out_size) {
    (void)in_sizes; (void)n_in; (void)out_size;
    const float* H    = (const float*)d_in[0];
    const float* Y    = (const float*)d_in[1];
    const float* W1   = (const float*)d_in[2];
    const float* b1   = (const float*)d_in[3];
    const float* W2   = (const float*)d_in[4];
    // d_in[5] = attn_b2: cancels in softmax.
    const float* W_ih = (const float*)d_in[6];
    const float* Whh  = (const float*)d_in[7];
    const float* b_ih = (const float*)d_in[8];
    const float* b_hh = (const float*)d_in[9];
    const float* fcW  = (const float*)d_in[10];
    const float* fcb  = (const float*)d_in[11];
    const float* fcfW = (const float*)d_in[12];
    const float* fcfb = (const float*)d_in[13];
    float* out = (float*)d_out;

    k_tr<<<dim3(4, 16), dim3(32, 8)>>>(Whh);
    k_pack<<<192, 256>>>(W1);
    k_init<<<Bz, 256>>>(H, W1, b1);
    for (int t = 0; t < Tz; ++t) {
        k_attn<<<Bz, 128>>>(W2);
        k_cell<<<Bz / BB, 256>>>(Y, W_ih, b_ih, b_hh, fcW, fcb, t);
    }
    k_final<<<Bz / 8, 256>>>(fcfW, fcfb, out);
}

// round 3
// speedup vs baseline: 4.8165x; 2.0536x over previous
#include <cuda_runtime.h>
#include <cuda_fp16.h>
#include <math.h>

#define Bz   2048
#define Tz   64
#define HZ   128   // HID
#define FZ   128   // FEAT
#define NB   16    // batch rows per persistent CTA
#define NT   512   // threads per CTA

typedef unsigned long long ull;

// ---------------- scratch (static device globals) ----------------
__device__ __half2 g_sPT[(size_t)Bz * FZ * (Tz / 2)];  // [b][f][t-pair] fp16x2 (32 MB)
__device__ __half  g_Hh [(size_t)Bz * Tz * HZ];        // [b][t][f] fp16 (32 MB)
__device__ float   g_WhT[HZ * 4 * HZ];                 // Whh transposed [128h][512j]
__device__ ull     g_WT2[HZ * 2 * FZ];                 // [h][pair][jj] fp32-pairs (i,f)/(g,o)
__device__ ull     g_W12[HZ * FZ];                     // [h][jj] fp32-pairs (W1d, W1c)

// ---------------- helpers ----------------
__device__ __forceinline__ float wred(float v) {
#pragma unroll
    for (int o = 16; o > 0; o >>= 1) v += __shfl_xor_sync(0xffffffffu, v, o);
    return v;
}
__device__ __forceinline__ float fast_tanh(float x) {       // accurate (~1e-7)
    float e = __expf(2.0f * x);
    return 1.0f - __fdividef(2.0f, e + 1.0f);
}
__device__ __forceinline__ float tanh_approx(float x) {     // MUFU.TANH
    float r; asm("tanh.approx.f32 %0, %1;" : "=f"(r) : "f"(x)); return r;
}
__device__ __forceinline__ float sigm(float x) {
    return __fdividef(1.0f, 1.0f + __expf(-x));
}
__device__ __forceinline__ ull pack2(float a, float b) {
    return (ull)__float_as_uint(a) | ((ull)__float_as_uint(b) << 32);
}
__device__ __forceinline__ float lo2(ull v) { return __uint_as_float((unsigned)v); }
__device__ __forceinline__ float hi2(ull v) { return __uint_as_float((unsigned)(v >> 32)); }
__device__ __forceinline__ void ffma2(ull &acc, ull a, ull b) {
    asm("fma.rn.f32x2 %0, %1, %2, %0;" : "+l"(acc) : "l"(a), "l"(b));
}

// ---------------------------------------------------------------------------
// k_tr: tiled transpose Whh [512,128] -> g_WhT [128,512]
// ---------------------------------------------------------------------------
__global__ void k_tr(const float* __restrict__ Whh) {
    __shared__ float tile[32][33];
    int tx = threadIdx.x, ty = threadIdx.y;
    int x = blockIdx.x * 32 + tx;
    int y = blockIdx.y * 32 + ty;
#pragma unroll
    for (int k = 0; k < 32; k += 8)
        tile[ty + k][tx] = Whh[(y + k) * HZ + x];
    __syncthreads();
    int x2 = blockIdx.y * 32 + tx;
    int y2 = blockIdx.x * 32 + ty;
#pragma unroll
    for (int k = 0; k < 32; k += 8)
        g_WhT[(y2 + k) * 512 + x2] = tile[tx][ty + k];
}

// ---------------------------------------------------------------------------
// k_pack: packed weight tables
// ---------------------------------------------------------------------------
__global__ void k_pack(const float* __restrict__ W1) {
    int idx = blockIdx.x * 256 + threadIdx.x;
    if (idx < HZ * 2 * FZ) {
        int jj = idx & 127, pair = (idx >> 7) & 1, h = idx >> 8;
        float v0 = g_WhT[h * 512 + pair * 256 + jj];
        float v1 = g_WhT[h * 512 + pair * 256 + 128 + jj];
        g_WT2[idx] = pack2(v0, v1);
    } else {
        int j = idx - HZ * 2 * FZ;
        int jj = j & 127, h = j >> 7;
        g_W12[j] = pack2(__ldg(&W1[h * FZ + jj]), __ldg(&W1[(128 + h) * FZ + jj]));
    }
}

// ---------------------------------------------------------------------------
// k_init: g_sPT[b][f][tp] = fp16(H@W1_h + b1) transposed; g_Hh = fp16(H).
// Grid Bz x 256, dynamic smem.
// ---------------------------------------------------------------------------
#define SMEM_INIT (HZ * 68 * 4 + 32 * 129 * 4)
__global__ void k_init(const float* __restrict__ H,
                       const float* __restrict__ W1,
                       const float* __restrict__ b1) {
    extern __shared__ char smraw[];
    float*    sHT    = (float*)smraw;                   // [128h][68pad]
    unsigned* sStage = (unsigned*)(smraw + HZ * 68 * 4); // [32tp][129pad]
    int b = blockIdx.x, tid = threadIdx.x;
    const float* Hb = H + (size_t)b * Tz * HZ;
    for (int i = tid; i < Tz * HZ; i += 256) {
        int t = i >> 7, h = i & 127;
        float v = Hb[i];
        sHT[h * 68 + t] = v;
        g_Hh[(size_t)b * Tz * HZ + i] = __float2half(v);
    }
    __syncthreads();

    int f = tid & 127, half_id = tid >> 7;
    float bias = __ldg(&b1[f]);
    ull acc[16];
#pragma unroll
    for (int k = 0; k < 16; ++k) acc[k] = pack2(bias, bias);

#pragma unroll 2
    for (int h = 0; h < HZ; ++h) {
        float w = __ldg(&W1[(256 + h) * FZ + f]);
        ull ww = pack2(w, w);
        const ull* row = (const ull*)&sHT[h * 68];
#pragma unroll
        for (int k = 0; k < 16; ++k)
            ffma2(acc[k], row[half_id * 16 + k], ww);
    }
#pragma unroll
    for (int k = 0; k < 16; ++k) {
        int tp = half_id * 16 + k;
        __half2 hv = __floats2half2_rn(lo2(acc[k]), hi2(acc[k]));
        sStage[tp * 129 + f] = *(unsigned*)&hv;
    }
    __syncthreads();
    unsigned* dst = (unsigned*)g_sPT + (size_t)b * (FZ * 32);
    for (int i = tid; i < FZ * 32; i += 256) {
        int ff = i >> 5, tp = i & 31;
        dst[i] = sStage[tp * 129 + ff];
    }
}

// ---------------------------------------------------------------------------
// k_main: persistent scan. Grid 128 CTAs x 512 threads; CTA owns NB=16 rows.
// ---------------------------------------------------------------------------
#define SMEM_MAIN (3 * NB * HZ * 4 + 2 * NB * HZ * 8 + FZ * 4 + NB * 4)
__global__ void __launch_bounds__(NT, 1)
k_main(const float* __restrict__ Y,
       const float* __restrict__ W2,
       const float* __restrict__ W_ih,
       const float* __restrict__ b_ih,
       const float* __restrict__ b_hh,
       const float* __restrict__ fcW,
       const float* __restrict__ fcb,
       const float* __restrict__ fcfW,
       const float* __restrict__ fcfb,
       float* __restrict__ out) {
    extern __shared__ char smraw[];
    float* sa   = (float*)smraw;             // [NB][128] a-vector
    float* sc   = sa + NB * HZ;              // [NB][128] c-state
    float* sctx = sc + NB * HZ;              // [NB][128] final-step ctx
    ull*   sdd  = (ull*)(sctx + NB * HZ);    // [NB][128] (d,d)
    ull*   sdc  = sdd + NB * HZ;             // [NB][128] (dn,cn)
    float* sw2  = (float*)(sdc + NB * HZ);   // [128]
    float* sy   = sw2 + FZ;                  // [NB]

    int tid = threadIdx.x, w = tid >> 5, lane = tid & 31;
    int b0 = blockIdx.x * NB;
    int jj = tid & 127, b4 = tid >> 7;

    for (int i = tid; i < NB * HZ; i += NT) { sa[i] = 0.0f; sc[i] = 0.0f; sdd[i] = 0ull; }
    if (tid < FZ) sw2[tid] = __ldg(&W2[tid]);

    // per-thread constants
    float wih0 = __ldg(&W_ih[jj]),        wih1 = __ldg(&W_ih[jj + 128]);
    float wih2 = __ldg(&W_ih[jj + 256]),  wih3 = __ldg(&W_ih[jj + 384]);
    float bia0 = __ldg(&b_ih[jj])       + __ldg(&b_hh[jj]);
    float bia1 = __ldg(&b_ih[jj + 128]) + __ldg(&b_hh[jj + 128]);
    float bia2 = __ldg(&b_ih[jj + 256]) + __ldg(&b_hh[jj + 256]);
    float bia3 = __ldg(&b_ih[jj + 384]) + __ldg(&b_hh[jj + 384]);
    float fw0 = __ldg(&fcW[2 * lane]),      fw1 = __ldg(&fcW[2 * lane + 1]);
    float fw2 = __ldg(&fcW[64 + 2 * lane]), fw3 = __ldg(&fcW[65 + 2 * lane]);
    float fwy = __ldg(&fcW[HZ]), fb0 = __ldg(&fcb[0]);

    int bl = w;                 // attention: warp w owns batch row bl=w
    int b  = b0 + bl;
    const __half2* pT  = g_sPT + (size_t)b * (FZ * 32);
    const __half2* Hb2 = (const __half2*)g_Hh + (size_t)b * (Tz * HZ / 2);
    __syncthreads();

    for (int step = 0; step < Tz; ++step) {
        // ---- e-scores: lane owns t = 2*lane, 2*lane+1 ----
        float s0 = 0.0f, s1 = 0.0f;
#pragma unroll 4
        for (int f = 0; f < FZ; ++f) {
            float2 v = __half22float2(pT[f * 32 + lane]);
            float af = sa[bl * HZ + f];
            float wf = sw2[f];
            s0 += tanh_approx(v.x + af) * wf;
            s1 += tanh_approx(v.y + af) * wf;
        }
        // ---- softmax over 64 (in-warp) ----
        float m = fmaxf(s0, s1);
#pragma unroll
        for (int o = 16; o > 0; o >>= 1) m = fmaxf(m, __shfl_xor_sync(0xffffffffu, m, o));
        float e0 = __expf(s0 - m), e1 = __expf(s1 - m);
        float ssum = wred(e0 + e1);
        float inv = __fdividef(1.0f, ssum);
        float beta0 = e0 * inv, beta1 = e1 * inv;

        // ---- ctx: lane accumulates f = 2l,2l+1,64+2l,65+2l ----
        float c0 = 0.0f, c1 = 0.0f, c2 = 0.0f, c3 = 0.0f;
#pragma unroll 8
        for (int t = 0; t < Tz; ++t) {
            float bb = __shfl_sync(0xffffffffu, (t & 1) ? beta1 : beta0, t >> 1);
            float2 h0 = __half22float2(Hb2[t * 64 + lane]);
            float2 h1 = __half22float2(Hb2[t * 64 + lane + 32]);
            c0 += bb * h0.x; c1 += bb * h0.y;
            c2 += bb * h1.x; c3 += bb * h1.y;
        }
        if (step == Tz - 1) {
            sctx[bl * HZ + 2 * lane]      = c0;
            sctx[bl * HZ + 2 * lane + 1]  = c1;
            sctx[bl * HZ + 64 + 2 * lane] = c2;
            sctx[bl * HZ + 65 + 2 * lane] = c3;
        }
        // ---- y_tilde (from ctx registers directly) ----
        float sdot = c0 * fw0 + c1 * fw1 + c2 * fw2 + c3 * fw3;
        sdot = wred(sdot);
        if (lane == 0)
            sy[bl] = sdot + __ldg(&Y[b * Tz + step]) * fwy + fb0;

        // ---- gates GEMV: all 512 threads; bl' = b4 + 4r ----
        ull acc[4][2];
#pragma unroll
        for (int r = 0; r < 4; ++r) { acc[r][0] = 0ull; acc[r][1] = 0ull; }
#pragma unroll 1
        for (int hc = 0; hc < 16; ++hc) {
            ull wv[16];
#pragma unroll
            for (int u = 0; u < 8; ++u) {
                wv[2 * u]     = __ldg(&g_WT2[((hc * 8 + u) * 2)     * 128 + jj]);
                wv[2 * u + 1] = __ldg(&g_WT2[((hc * 8 + u) * 2 + 1) * 128 + jj]);
            }
#pragma unroll
            for (int u = 0; u < 8; ++u) {
                int h = hc * 8 + u;
#pragma unroll
                for (int r = 0; r < 4; ++r) {
                    ull dv = sdd[(b4 + 4 * r) * HZ + h];
                    ffma2(acc[r][0], dv, wv[2 * u]);
                    ffma2(acc[r][1], dv, wv[2 * u + 1]);
                }
            }
        }
        __syncthreads();   // done reading sdd; sy ready

        // ---- LSTM pointwise ----
#pragma unroll
        for (int r = 0; r < 4; ++r) {
            int blr = b4 + 4 * r;
            float yt = sy[blr];
            float gi = lo2(acc[r][0]) + yt * wih0 + bia0;
            float gf = hi2(acc[r][0]) + yt * wih1 + bia1;
            float gg = lo2(acc[r][1]) + yt * wih2 + bia2;
            float go = hi2(acc[r][1]) + yt * wih3 + bia3;
            float cold = sc[blr * HZ + jj];
            float cn = sigm(gf) * cold + sigm(gi) * fast_tanh(gg);
            float dn = sigm(go) * fast_tanh(cn);
            sc[blr * HZ + jj]  = cn;
            sdc[blr * HZ + jj] = pack2(dn, cn);
            sdd[blr * HZ + jj] = pack2(dn, dn);
        }
        __syncthreads();   // sdc ready

        // ---- a_next = [d,c] @ W1_dc ----
        ull aa[4];
#pragma unroll
        for (int r = 0; r < 4; ++r) aa[r] = 0ull;
#pragma unroll 1
        for (int hc = 0; hc < 16; ++hc) {
            ull wv[8];
#pragma unroll
            for (int u = 0; u < 8; ++u)
                wv[u] = __ldg(&g_W12[(hc * 8 + u) * 128 + jj]);
#pragma unroll
            for (int u = 0; u < 8; ++u) {
                int h = hc * 8 + u;
#pragma unroll
                for (int r = 0; r < 4; ++r)
                    ffma2(aa[r], sdc[(b4 + 4 * r) * HZ + h], wv[u]);
            }
        }
#pragma unroll
        for (int r = 0; r < 4; ++r)
            sa[(b4 + 4 * r) * HZ + jj] = lo2(aa[r]) + hi2(aa[r]);
        __syncthreads();   // sa/sdd ready for next step
    }

    // ---- final: out[b] = d.fcf[0:128] + ctx.fcf[128:256] + fcfb ----
    float s = 0.0f;
#pragma unroll
    for (int k = 0; k < 4; ++k) {
        int f = lane + 32 * k;
        s += lo2(sdd[bl * HZ + f]) * __ldg(&fcfW[f]) + sctx[bl * HZ + f] * __ldg(&fcfW[128 + f]);
    }
    s = wred(s);
    if (lane == 0) out[b] = s + __ldg(&fcfb[0]);
}

extern "C" void kernel_launch(void* const* d_in, const int* in_sizes, int n_in,
                              void* d_out, int out_size) {
    (void)in_sizes; (void)n_in; (void)out_size;
    const float* H    = (const float*)d_in[0];
    const float* Y    = (const float*)d_in[1];
    const float* W1   = (const float*)d_in[2];
    const float* b1   = (const float*)d_in[3];
    const float* W2   = (const float*)d_in[4];
    // d_in[5] = attn_b2: cancels in softmax.
    const float* W_ih = (const float*)d_in[6];
    const float* Whh  = (const float*)d_in[7];
    const float* b_ih = (const float*)d_in[8];
    const float* b_hh = (const float*)d_in[9];
    const float* fcW  = (const float*)d_in[10];
    const float* fcb  = (const float*)d_in[11];
    const float* fcfW = (const float*)d_in[12];
    const float* fcfb = (const float*)d_in[13];
    float* out = (float*)d_out;

    static int configured = 0;
    if (!configured) {
        cudaFuncSetAttribute(k_init, cudaFuncAttributeMaxDynamicSharedMemorySize, SMEM_INIT);
        cudaFuncSetAttribute(k_main, cudaFuncAttributeMaxDynamicSharedMemorySize, SMEM_MAIN);
        configured = 1;
    }

    k_tr<<<dim3(4, 16), dim3(32, 8)>>>(Whh);
    k_pack<<<192, 256>>>(W1);
    k_init<<<Bz, 256, SMEM_INIT>>>(H, W1, b1);
    k_main<<<Bz / NB, NT, SMEM_MAIN>>>(Y, W2, W_ih, b_ih, b_hh, fcW, fcb, fcfW, fcfb, out);
}